// round 5
// baseline (speedup 1.0000x reference)
#include <cuda_runtime.h>
#include <cstdint>

#define N_      2048
#define T_      512
#define B_      32
#define NCTA    128
#define NLOC    16          // neurons per CTA
#define NTHR    512
#define CJ      256         // A j-chunk size
#define NCHUNK  8
#define RP      36          // padded row stride in floats (144B)

#define DT_     1e-4f
#define U_C     0.3f
#define TAU_    0.008f
#define TAU_F   1.5f
#define TAU_D   0.3f
#define ALPHA_  1.5f
#define I_B_    8.0f
#define J_EI_   1.1f
#define J_IE_   2.2f

// output layout: tuple (all_h, all_u, all_x, all_hI, outputs) concatenated
#define OFF_H   ((size_t)0)
#define OFF_U   ((size_t)T_ * B_ * N_)
#define OFF_X   ((size_t)2 * T_ * B_ * N_)
#define OFF_HI  ((size_t)3 * T_ * B_ * N_)
#define OFF_OUT (OFF_HI + (size_t)T_ * B_)

// ---- static device scratch (no allocation) ----
__device__ float g_A[2][N_ * B_];          // activation u*x*R, [j][b], double buffered
__device__ float g_pR[2][NCTA * B_];       // per-CTA partial sum R
__device__ float g_pO[2][NCTA * B_];       // per-CTA partial sum R*W_out
__device__ unsigned int g_flag[2][NCTA];   // publish flags (monotonic step counters)
__device__ unsigned int g_exit  = 0;       // exit barrier
__device__ unsigned int g_exit2 = 0;

// smem layout (floats)
#define WT_STRIDE   (2 * 16 * RP)              // 1152 floats per warp tile (2 slots)
#define SLOT_BYTES  (16 * RP * 4)              // 2304 B per slot
#define SM_PART     (16 * WT_STRIDE)           // 18432
#define SMEM_FLOATS (SM_PART + 256 * RP + 16)
#define SMEM_BYTES  (SMEM_FLOATS * 4)          // ~110.7 KB

// R(h) = ALPHA * softplus(h/ALPHA), numerically stable
__device__ __forceinline__ float rate_fn(float h) {
    float z  = h * (1.0f / ALPHA_);
    float sp = fmaxf(z, 0.0f) + log1pf(__expf(-fabsf(z)));
    return ALPHA_ * sp;
}

// ---- packed f32x2 helpers (Blackwell) ----
__device__ __forceinline__ unsigned long long pack2(float v) {
    unsigned long long r;
    asm("mov.b64 %0, {%1, %1};" : "=l"(r) : "f"(v));
    return r;
}
__device__ __forceinline__ void fma2(unsigned long long& d,
                                     unsigned long long a,
                                     unsigned long long b) {
    asm("fma.rn.f32x2 %0, %1, %2, %0;" : "+l"(d) : "l"(a), "l"(b));
}
__device__ __forceinline__ unsigned long long add2(unsigned long long a,
                                                   unsigned long long b) {
    unsigned long long r;
    asm("add.rn.f32x2 %0, %1, %2;" : "=l"(r) : "l"(a), "l"(b));
    return r;
}

// ---- cp.async helpers ----
__device__ __forceinline__ void cp_async16(uint32_t smem_addr, const void* gptr) {
    asm volatile("cp.async.cg.shared.global [%0], [%1], 16;"
                 :: "r"(smem_addr), "l"(gptr));
}
__device__ __forceinline__ void cp_commit() {
    asm volatile("cp.async.commit_group;");
}
template <int NKeep>
__device__ __forceinline__ void cp_wait() {
    asm volatile("cp.async.wait_group %0;" :: "n"(NKeep));
}

// ---- release/acquire flag ops ----
__device__ __forceinline__ unsigned ld_acq(const unsigned* p) {
    unsigned v;
    asm volatile("ld.acquire.gpu.global.b32 %0, [%1];" : "=r"(v) : "l"(p));
    return v;
}
__device__ __forceinline__ void st_rel(unsigned* p, unsigned v) {
    asm volatile("st.release.gpu.global.b32 [%0], %1;" :: "l"(p), "r"(v));
}
// wait until the 16 flags f[0..15] are all >= need (lanes 0-15 poll, warp syncs)
__device__ __forceinline__ void poll16(const unsigned* f, int need) {
    if ((threadIdx.x & 31) < 16) {
        const unsigned* p = f + (threadIdx.x & 15);
        while ((int)ld_acq(p) < need) { }
    }
    __syncwarp();
}

__global__ void __launch_bounds__(NTHR, 1)
stp_kernel(const float* __restrict__ inp,    // [T,B,1]
           const float* __restrict__ W_in,   // [N,1]
           const float* __restrict__ J,      // [N,N]
           const float* __restrict__ W_out,  // [1,N]
           float* __restrict__ out)
{
    extern __shared__ float sm[];
    float* part = sm + SM_PART;   // [256][RP]

    const int tid  = threadIdx.x;
    const int cta  = blockIdx.x;
    const int il   = tid & 15;          // local neuron 0..15
    const int s    = tid >> 4;          // j-slice 0..31 == batch b
    const int b    = s;
    const int lane = tid & 31;
    const int warp = tid >> 5;
    const int p    = s & 1;             // half-warp parity
    const int i    = cta * NLOC + il;   // global neuron
    const int c0   = cta >> 4;          // this CTA's own chunk (ready first)

    float* warpTile = sm + warp * WT_STRIDE;
    const uint32_t wt_base = (uint32_t)__cvta_generic_to_shared(warpTile);

    // per-lane staging map: 4 cp.async16 ops cover this warp's 16 rows x 128B
    int goff[4], soff[4];
    #pragma unroll
    for (int o = 0; o < 4; ++o) {
        int n   = o * 32 + lane;
        int row = n >> 3;           // 0..15
        int seg = n & 7;            // 16B segment
        int jin = (row >> 1) * 32 + 2 * warp + (row & 1);   // j within chunk
        goff[o] = jin * B_ + seg * 4;                       // floats
        soff[o] = (row * RP + seg * 4) * 4;                 // bytes within slot
    }

    // ---- load this thread's 64 J coefficients, in chunk-iteration order ----
    float Jreg[64];
    {
        const float* Jrow = J + (size_t)i * N_;
        #pragma unroll
        for (int cc = 0; cc < 8; ++cc) {
            const int c = (c0 + cc) & 7;
            #pragma unroll
            for (int q = 0; q < 8; ++q)
                Jreg[cc * 8 + q] = __ldg(&Jrow[c * CJ + q * 32 + s]);
        }
    }

    // ---- init state ----
    float h = 0.0f, u = U_C, x = 1.0f, hI = 0.0f;
    const float wi = __ldg(&W_in[i]);
    const float wo = __ldg(&W_out[i]);

    // ---- publish A0, pR0, flag0 ----
    float Rcur = rate_fn(h);
    {
        float A0 = u * x * Rcur;
        __stcg(&g_A[0][(size_t)i * B_ + b], A0);
        float sR = Rcur;
        #pragma unroll
        for (int o = 8; o > 0; o >>= 1) sR += __shfl_xor_sync(0xffffffffu, sR, o);
        if (il == 0) __stcg(&g_pR[0][cta * B_ + b], sR);
    }
    __threadfence();
    __syncthreads();
    if (tid == 0) st_rel(&g_flag[0][cta], 1u);

    for (int t = 0; t < T_; ++t) {
        const int buf  = t & 1;
        const int nbuf = buf ^ 1;
        const int need = t + 1;
        const float* gA = g_A[buf];
        const float* pR = g_pR[buf];
        const float* pO = g_pO[buf];

        float sumR_th = 0.0f, sumO_th = 0.0f;

        // prologue: chunk c0 into slot 0
        {
            poll16(&g_flag[buf][c0 * 16], need);
            const float* src = gA + c0 * (CJ * B_);
            #pragma unroll
            for (int o = 0; o < 4; ++o)
                cp_async16(wt_base + soff[o], src + goff[o]);
            cp_commit();
            sumR_th += __ldcg(&pR[(c0 * 16 + il) * B_ + s]);
            if (cta == 0) sumO_th += __ldcg(&pO[(c0 * 16 + il) * B_ + s]);
        }

        unsigned long long acc2[16];
        #pragma unroll
        for (int m = 0; m < 16; ++m) acc2[m] = 0ull;

        #pragma unroll
        for (int cc = 0; cc < NCHUNK; ++cc) {
            if (cc < NCHUNK - 1) {
                const int cn = (c0 + cc + 1) & 7;
                poll16(&g_flag[buf][cn * 16], need);
                const uint32_t sb = wt_base + ((cc + 1) & 1) * SLOT_BYTES;
                const float* src = gA + cn * (CJ * B_);
                #pragma unroll
                for (int o = 0; o < 4; ++o)
                    cp_async16(sb + soff[o], src + goff[o]);
                cp_commit();
                sumR_th += __ldcg(&pR[(cn * 16 + il) * B_ + s]);
                if (cta == 0) sumO_th += __ldcg(&pO[(cn * 16 + il) * B_ + s]);
                cp_wait<1>();
            } else {
                cp_wait<0>();
            }
            // compute chunk cc from slot cc&1
            const float* Ab = warpTile + (cc & 1) * (16 * RP);
            #pragma unroll
            for (int q = 0; q < 8; ++q) {
                unsigned long long jp = pack2(Jreg[cc * 8 + q]);
                const ulonglong2* a8 = (const ulonglong2*)(Ab + (2 * q + p) * RP);
                #pragma unroll
                for (int e = 0; e < 8; ++e) {
                    ulonglong2 v = a8[e];
                    fma2(acc2[2 * e],     v.x, jp);
                    fma2(acc2[2 * e + 1], v.y, jp);
                }
            }
        }

        // --- combine the two half-warp j-slices, dump to part ---
        #pragma unroll
        for (int m = 0; m < 16; ++m) {
            unsigned long long o = __shfl_xor_sync(0xffffffffu, acc2[m], 16);
            acc2[m] = add2(acc2[m], o);
        }
        if (p == 0) {
            unsigned long long* dst = (unsigned long long*)(part + (warp * 16 + il) * RP);
            #pragma unroll
            for (int m = 0; m < 16; ++m) dst[m] = acc2[m];
        }
        __syncthreads();

        // --- gather: thread (il, b) sums its 16 warp-partials ---
        float syn = 0.0f;
        #pragma unroll
        for (int k = 0; k < 16; ++k)
            syn += part[(k * 16 + il) * RP + b];

        // --- finish sumR / sumO (reduce over il via butterfly) ---
        #pragma unroll
        for (int o = 1; o <= 8; o <<= 1)
            sumR_th += __shfl_xor_sync(0xffffffffu, sumR_th, o);
        if (cta == 0) {
            #pragma unroll
            for (int o = 1; o <= 8; o <<= 1)
                sumO_th += __shfl_xor_sync(0xffffffffu, sumO_th, o);
            if (t > 0 && il == 0)
                out[OFF_OUT + (size_t)(t - 1) * B_ + b] = sumO_th;
        }

        // --- state update ---
        float Ie  = __ldg(&inp[t * B_ + b]) * wi;
        float RI  = rate_fn(hI);
        float dh  = (-h + syn + I_B_ + Ie) * (1.0f / TAU_) - J_EI_ * RI * (1.0f / TAU_);
        float du  = (U_C - u) * (1.0f / TAU_F) + U_C * (1.0f - u) * Rcur;
        float dx  = (1.0f - x) * (1.0f / TAU_D) - u * x * Rcur;
        float dhI = (-hI + J_IE_ * sumR_th) * (1.0f / TAU_);
        h  += dh  * DT_;
        u  += du  * DT_;
        x  += dx  * DT_;
        hI += dhI * DT_;

        // --- write state outputs ---
        const size_t row = (size_t)(t * B_ + b) * N_ + i;
        __stcs(&out[OFF_H + row], h);
        __stcs(&out[OFF_U + row], u);
        __stcs(&out[OFF_X + row], x);
        if (cta == 0 && il == 0)
            out[OFF_HI + (size_t)t * B_ + b] = hI;

        // --- publish next-step activation + partials, then flag ---
        Rcur = rate_fn(h);
        {
            float A2 = u * x * Rcur;
            __stcg(&g_A[nbuf][(size_t)i * B_ + b], A2);
            float sR = Rcur;
            float sO = Rcur * wo;
            #pragma unroll
            for (int o = 8; o > 0; o >>= 1) {
                sR += __shfl_xor_sync(0xffffffffu, sR, o);
                sO += __shfl_xor_sync(0xffffffffu, sO, o);
            }
            if (il == 0) {
                __stcg(&g_pR[nbuf][cta * B_ + b], sR);
                __stcg(&g_pO[nbuf][cta * B_ + b], sO);
            }
        }
        __threadfence();
        __syncthreads();                 // also protects 'part' WAR
        if (tid == 0) st_rel(&g_flag[nbuf][cta], (unsigned)(t + 2));
    }

    // --- final output row outputs[T-1] (CTA 0) ---
    if (cta == 0) {
        for (int base = 0; base < NCTA; base += 16)
            poll16(&g_flag[0][base], T_ + 1);
        float so = 0.0f;
        #pragma unroll
        for (int c = 0; c < 8; ++c)
            so += __ldcg(&g_pO[0][(c * 16 + il) * B_ + s]);
        #pragma unroll
        for (int o = 1; o <= 8; o <<= 1)
            so += __shfl_xor_sync(0xffffffffu, so, o);
        if (il == 0)
            out[OFF_OUT + (size_t)(T_ - 1) * B_ + b] = so;
    }

    // --- exit: reset flags for CUDA-graph replays ---
    __syncthreads();
    if (tid == 0) {
        __threadfence();
        atomicAdd(&g_exit, 1u);
        while (*(volatile unsigned int*)&g_exit < NCTA) { }
        g_flag[0][cta] = 0;
        g_flag[1][cta] = 0;
        __threadfence();
        unsigned v = atomicAdd(&g_exit2, 1u);
        if (v == NCTA - 1) {
            g_exit = 0;
            __threadfence();
            g_exit2 = 0;
        }
    }
}

extern "C" void kernel_launch(void* const* d_in, const int* in_sizes, int n_in,
                              void* d_out, int out_size) {
    const float* inp   = (const float*)d_in[0];
    const float* W_in  = (const float*)d_in[1];
    const float* J     = (const float*)d_in[2];
    const float* W_out = (const float*)d_in[3];
    float* out = (float*)d_out;

    static bool attr_done = false;
    if (!attr_done) {
        cudaFuncSetAttribute(stp_kernel,
                             cudaFuncAttributeMaxDynamicSharedMemorySize,
                             SMEM_BYTES);
        attr_done = true;
    }
    stp_kernel<<<NCTA, NTHR, SMEM_BYTES>>>(inp, W_in, J, W_out, out);
}

// round 6
// speedup vs baseline: 1.8535x; 1.8535x over previous
#include <cuda_runtime.h>
#include <cstdint>

#define N_      2048
#define T_      512
#define B_      32
#define NCTA    128
#define NLOC    16          // neurons per CTA
#define NTHR    512
#define CJ      256         // A j-chunk size
#define NCHUNK  8
#define RP      36          // padded row stride in floats (144B, 16B-aligned)
#define NSLOT   4

#define DT_     1e-4f
#define U_C     0.3f
#define TAU_    0.008f
#define TAU_F   1.5f
#define TAU_D   0.3f
#define ALPHA_  1.5f
#define I_B_    8.0f
#define J_EI_   1.1f
#define J_IE_   2.2f

// output layout: tuple (all_h, all_u, all_x, all_hI, outputs) concatenated
#define OFF_H   ((size_t)0)
#define OFF_U   ((size_t)T_ * B_ * N_)
#define OFF_X   ((size_t)2 * T_ * B_ * N_)
#define OFF_HI  ((size_t)3 * T_ * B_ * N_)
#define OFF_OUT (OFF_HI + (size_t)T_ * B_)

// ---- static device scratch (no allocation) ----
__device__ __align__(128) float g_A[2][N_ * B_];   // u*x*R, [j][b], double buffered
__device__ __align__(128) float g_pR[2][NCTA * B_];
__device__ __align__(128) float g_pO[2][NCTA * B_];
__device__ unsigned int g_bar  = 0;       // monotonic grid barrier counter
__device__ unsigned int g_exit = 0;       // exit counter (resets g_bar for replays)

// smem layout (floats): warp tiles then part
#define SLOT_F      (16 * RP)                       // 576 floats per slot
#define SLOT_BYTES  (SLOT_F * 4)                    // 2304 B
#define WT_F        (NSLOT * SLOT_F)                // 2304 floats per warp
#define SM_PART     (16 * WT_F)                     // 36864
#define SMEM_FLOATS (SM_PART + 256 * RP + 16)       // + 9216 + 16
#define SMEM_BYTES  (SMEM_FLOATS * 4)               // 184384 B

// R(h) = ALPHA * softplus(h/ALPHA), numerically stable
__device__ __forceinline__ float rate_fn(float h) {
    float z  = h * (1.0f / ALPHA_);
    float sp = fmaxf(z, 0.0f) + log1pf(__expf(-fabsf(z)));
    return ALPHA_ * sp;
}

// ---- packed f32x2 helpers ----
__device__ __forceinline__ unsigned long long pack2(float v) {
    unsigned long long r;
    asm("mov.b64 %0, {%1, %1};" : "=l"(r) : "f"(v));
    return r;
}
__device__ __forceinline__ void fma2(unsigned long long& d,
                                     unsigned long long a,
                                     unsigned long long b) {
    asm("fma.rn.f32x2 %0, %1, %2, %0;" : "+l"(d) : "l"(a), "l"(b));
}
__device__ __forceinline__ unsigned long long add2(unsigned long long a,
                                                   unsigned long long b) {
    unsigned long long r;
    asm("add.rn.f32x2 %0, %1, %2;" : "=l"(r) : "l"(a), "l"(b));
    return r;
}

// ---- cp.async helpers ----
__device__ __forceinline__ void cp_async16(uint32_t smem_addr, const void* gptr) {
    asm volatile("cp.async.cg.shared.global [%0], [%1], 16;"
                 :: "r"(smem_addr), "l"(gptr));
}
__device__ __forceinline__ void cp_commit() {
    asm volatile("cp.async.commit_group;");
}
template <int NKeep>
__device__ __forceinline__ void cp_wait() {
    asm volatile("cp.async.wait_group %0;" :: "n"(NKeep));
}

__global__ void __launch_bounds__(NTHR, 1)
stp_kernel(const float* __restrict__ inp,    // [T,B,1]
           const float* __restrict__ W_in,   // [N,1]
           const float* __restrict__ J,      // [N,N]
           const float* __restrict__ W_out,  // [1,N]
           float* __restrict__ out)
{
    extern __shared__ float sm[];
    float* part = sm + SM_PART;   // [256][RP]

    const int tid  = threadIdx.x;
    const int cta  = blockIdx.x;
    const int il   = tid & 15;          // local neuron 0..15
    const int s    = tid >> 4;          // j-slice 0..31 == batch b
    const int b    = s;
    const int lane = tid & 31;
    const int warp = tid >> 5;
    const int p    = s & 1;             // half-warp parity
    const int i    = cta * NLOC + il;   // global neuron
    const int c0   = cta >> 4;          // chunk rotation (spread L2 traffic)

    float* warpTile = sm + warp * WT_F;
    const uint32_t wt_base = (uint32_t)__cvta_generic_to_shared(warpTile);

    // ---- load this thread's 64 J coefficients, in chunk-iteration order ----
    float Jreg[64];
    {
        const float* Jrow = J + (size_t)i * N_;
        #pragma unroll
        for (int cc = 0; cc < 8; ++cc) {
            const int c = (c0 + cc) & 7;
            #pragma unroll
            for (int q = 0; q < 8; ++q)
                Jreg[cc * 8 + q] = __ldg(&Jrow[c * CJ + q * 32 + s]);
        }
    }

    // ---- init state ----
    float h = 0.0f, u = U_C, x = 1.0f, hI = 0.0f;
    const float wi = __ldg(&W_in[i]);
    const float wo = __ldg(&W_out[i]);

    // ---- publish A0, pR0 ----
    float Rcur = rate_fn(h);
    {
        float A0 = u * x * Rcur;
        __stcg(&g_A[0][(size_t)i * B_ + b], A0);
        float sR = Rcur;
        #pragma unroll
        for (int o = 8; o > 0; o >>= 1) sR += __shfl_xor_sync(0xffffffffu, sR, o);
        if (il == 0) __stcg(&g_pR[0][cta * B_ + b], sR);
    }
    __syncthreads();
    if (tid == 0) {
        __threadfence();
        atomicAdd(&g_bar, 1u);
        while (*(volatile unsigned int*)&g_bar < (unsigned)NCTA) { }
        __threadfence();
    }
    __syncthreads();

    for (int t = 0; t < T_; ++t) {
        const int buf  = t & 1;
        const int nbuf = buf ^ 1;
        const float* gA = g_A[buf];

        // stage chunk (c0+cc)&7 into slot cc&3 (warp-private, no CTA sync)
        auto stage = [&](int cc) {
            const int chunk = (c0 + cc) & 7;
            const float* src = gA + chunk * (CJ * B_);
            const uint32_t sb = wt_base + (uint32_t)((cc & 3) * SLOT_BYTES);
            #pragma unroll
            for (int o = 0; o < 4; ++o) {
                int n   = o * 32 + lane;
                int row = n >> 3;
                int seg = n & 7;
                int jin = (row >> 1) * 32 + 2 * warp + (row & 1);
                cp_async16(sb + (uint32_t)((row * RP + seg * 4) * 4),
                           src + jin * B_ + seg * 4);
            }
            cp_commit();
        };

        // prologue: 3 chunks in flight
        stage(0); stage(1); stage(2);

        const float inval = __ldg(&inp[t * B_ + b]);

        unsigned long long acc2[16];
        #pragma unroll
        for (int m = 0; m < 16; ++m) acc2[m] = 0ull;

        #pragma unroll
        for (int cc = 0; cc < NCHUNK; ++cc) {
            if (cc + 3 < NCHUNK) stage(cc + 3);
            if      (cc < 5) cp_wait<3>();
            else if (cc == 5) cp_wait<2>();
            else if (cc == 6) cp_wait<1>();
            else              cp_wait<0>();
            __syncwarp();

            const float* Ab = warpTile + (cc & 3) * SLOT_F;
            #pragma unroll
            for (int q = 0; q < 8; ++q) {
                unsigned long long jp = pack2(Jreg[cc * 8 + q]);
                const ulonglong2* a8 = (const ulonglong2*)(Ab + (2 * q + p) * RP);
                #pragma unroll
                for (int e = 0; e < 8; ++e) {
                    ulonglong2 v = a8[e];
                    fma2(acc2[2 * e],     v.x, jp);
                    fma2(acc2[2 * e + 1], v.y, jp);
                }
            }
        }

        // --- launch pR/pO gathers (latency overlaps part-reduce below) ---
        float rv[8];
        #pragma unroll
        for (int k = 0; k < 8; ++k)
            rv[k] = __ldcg(&g_pR[buf][(il * 8 + k) * B_ + b]);
        float ov[8];
        if (cta == 0) {
            #pragma unroll
            for (int k = 0; k < 8; ++k)
                ov[k] = __ldcg(&g_pO[buf][(il * 8 + k) * B_ + b]);
        }

        // --- combine the two half-warp j-slices, dump to part ---
        #pragma unroll
        for (int m = 0; m < 16; ++m) {
            unsigned long long o = __shfl_xor_sync(0xffffffffu, acc2[m], 16);
            acc2[m] = add2(acc2[m], o);
        }
        if (p == 0) {
            ulonglong2* dst = (ulonglong2*)(part + (warp * 16 + il) * RP);
            #pragma unroll
            for (int m = 0; m < 8; ++m)
                dst[m] = make_ulonglong2(acc2[2 * m], acc2[2 * m + 1]);
        }
        __syncthreads();

        // --- gather: thread (il, b) sums its 16 warp-partials ---
        float syn = 0.0f;
        #pragma unroll
        for (int k = 0; k < 16; ++k)
            syn += part[(k * 16 + il) * RP + b];

        // --- finish sumR / sumO ---
        float sumR = rv[0] + rv[1] + rv[2] + rv[3] + rv[4] + rv[5] + rv[6] + rv[7];
        #pragma unroll
        for (int o = 1; o <= 8; o <<= 1)
            sumR += __shfl_xor_sync(0xffffffffu, sumR, o);
        if (cta == 0) {
            float sumO = ov[0] + ov[1] + ov[2] + ov[3] + ov[4] + ov[5] + ov[6] + ov[7];
            #pragma unroll
            for (int o = 1; o <= 8; o <<= 1)
                sumO += __shfl_xor_sync(0xffffffffu, sumO, o);
            if (t > 0 && il == 0)
                out[OFF_OUT + (size_t)(t - 1) * B_ + b] = sumO;
        }

        // --- state update ---
        float Ie  = inval * wi;
        float RI  = rate_fn(hI);
        float dh  = (-h + syn + I_B_ + Ie) * (1.0f / TAU_) - J_EI_ * RI * (1.0f / TAU_);
        float du  = (U_C - u) * (1.0f / TAU_F) + U_C * (1.0f - u) * Rcur;
        float dx  = (1.0f - x) * (1.0f / TAU_D) - u * x * Rcur;
        float dhI = (-hI + J_IE_ * sumR) * (1.0f / TAU_);
        h  += dh  * DT_;
        u  += du  * DT_;
        x  += dx  * DT_;
        hI += dhI * DT_;

        // --- publish next-step activation + partials ---
        Rcur = rate_fn(h);
        {
            float A2 = u * x * Rcur;
            __stcg(&g_A[nbuf][(size_t)i * B_ + b], A2);
            float sR = Rcur;
            float sO = Rcur * wo;
            #pragma unroll
            for (int o = 8; o > 0; o >>= 1) {
                sR += __shfl_xor_sync(0xffffffffu, sR, o);
                sO += __shfl_xor_sync(0xffffffffu, sO, o);
            }
            if (il == 0) {
                __stcg(&g_pR[nbuf][cta * B_ + b], sR);
                __stcg(&g_pO[nbuf][cta * B_ + b], sO);
            }
        }

        // --- barrier: arrive early, overlap output writes with propagation ---
        __syncthreads();                       // publish stores + part WAR
        if (tid == 0) {
            __threadfence();
            atomicAdd(&g_bar, 1u);
        }
        const size_t row = (size_t)(t * B_ + b) * N_ + i;
        __stcs(&out[OFF_H + row], h);
        __stcs(&out[OFF_U + row], u);
        __stcs(&out[OFF_X + row], x);
        if (cta == 0 && il == 0)
            out[OFF_HI + (size_t)t * B_ + b] = hI;
        if (tid == 0) {
            while (*(volatile unsigned int*)&g_bar < (unsigned)NCTA * (unsigned)(t + 2)) { }
            __threadfence();
        }
        __syncthreads();
    }

    // --- final output row outputs[T-1] (CTA 0); pO[0] published at t=511 ---
    if (cta == 0) {
        float so = 0.0f;
        #pragma unroll
        for (int k = 0; k < 8; ++k)
            so += __ldcg(&g_pO[0][(il * 8 + k) * B_ + b]);
        #pragma unroll
        for (int o = 1; o <= 8; o <<= 1)
            so += __shfl_xor_sync(0xffffffffu, so, o);
        if (il == 0)
            out[OFF_OUT + (size_t)(T_ - 1) * B_ + b] = so;
    }

    // --- reset barrier counter for CUDA-graph replays ---
    __syncthreads();
    if (tid == 0) {
        __threadfence();
        unsigned v = atomicAdd(&g_exit, 1u);
        if (v == NCTA - 1) {
            g_bar  = 0;
            g_exit = 0;
            __threadfence();
        }
    }
}

extern "C" void kernel_launch(void* const* d_in, const int* in_sizes, int n_in,
                              void* d_out, int out_size) {
    const float* inp   = (const float*)d_in[0];
    const float* W_in  = (const float*)d_in[1];
    const float* J     = (const float*)d_in[2];
    const float* W_out = (const float*)d_in[3];
    float* out = (float*)d_out;

    static bool attr_done = false;
    if (!attr_done) {
        cudaFuncSetAttribute(stp_kernel,
                             cudaFuncAttributeMaxDynamicSharedMemorySize,
                             SMEM_BYTES);
        attr_done = true;
    }
    stp_kernel<<<NCTA, NTHR, SMEM_BYTES>>>(inp, W_in, J, W_out, out);
}

// round 9
// speedup vs baseline: 1.9596x; 1.0572x over previous
#include <cuda_runtime.h>
#include <cstdint>

#define N_      2048
#define T_      512
#define B_      32
#define NCTA    256
#define NLOC    8           // neurons per CTA
#define NTHR    256
#define CJ      128         // A j-chunk size
#define NCHUNK  16
#define RP      36          // padded row stride (floats) = 144B
#define NSLOT   4

#define DT_     1e-4f
#define U_C     0.3f
#define TAU_    0.008f
#define TAU_F   1.5f
#define TAU_D   0.3f
#define ALPHA_  1.5f
#define I_B_    8.0f
#define J_EI_   1.1f
#define J_IE_   2.2f

// output layout: tuple (all_h, all_u, all_x, all_hI, outputs) concatenated
#define OFF_H   ((size_t)0)
#define OFF_U   ((size_t)T_ * B_ * N_)
#define OFF_X   ((size_t)2 * T_ * B_ * N_)
#define OFF_HI  ((size_t)3 * T_ * B_ * N_)
#define OFF_OUT (OFF_HI + (size_t)T_ * B_)

// ---- static device scratch ----
__device__ __align__(128) float g_A[2][N_ * B_];     // u*x*R, [j][b]
__device__ __align__(128) float g_pR[2][B_ * NCTA];  // transposed: [b][cta]
__device__ __align__(128) float g_pO[2][B_ * NCTA];  // transposed: [b][cta]
__device__ unsigned int g_bar  = 0;
__device__ unsigned int g_exit = 0;

// smem layout (floats)
#define SLOT_F      (16 * RP)                 // 576
#define SLOT_BYTES  (SLOT_F * 4)              // 2304
#define WT_F        (NSLOT * SLOT_F)          // 2304
#define SM_PART     (8 * WT_F)                // 18432 (8 warps)
#define SMEM_FLOATS (SM_PART + 128 * RP + 16) // + 4608 + 16
#define SMEM_BYTES  (SMEM_FLOATS * 4)         // 92224 B  (2 CTAs/SM fit)

__device__ __forceinline__ float rate_fn(float h) {
    float z  = h * (1.0f / ALPHA_);
    float sp = fmaxf(z, 0.0f) + log1pf(__expf(-fabsf(z)));
    return ALPHA_ * sp;
}

// ---- packed f32x2 helpers ----
__device__ __forceinline__ unsigned long long pack2(float v) {
    unsigned long long r;
    asm("mov.b64 %0, {%1, %1};" : "=l"(r) : "f"(v));
    return r;
}
__device__ __forceinline__ void fma2(unsigned long long& d,
                                     unsigned long long a,
                                     unsigned long long b) {
    asm("fma.rn.f32x2 %0, %1, %2, %0;" : "+l"(d) : "l"(a), "l"(b));
}
__device__ __forceinline__ unsigned long long add2(unsigned long long a,
                                                   unsigned long long b) {
    unsigned long long r;
    asm("add.rn.f32x2 %0, %1, %2;" : "=l"(r) : "l"(a), "l"(b));
    return r;
}

// ---- cp.async helpers ----
__device__ __forceinline__ void cp_async16(uint32_t smem_addr, const void* gptr) {
    asm volatile("cp.async.cg.shared.global [%0], [%1], 16;"
                 :: "r"(smem_addr), "l"(gptr));
}
__device__ __forceinline__ void cp_commit() {
    asm volatile("cp.async.commit_group;");
}
template <int NKeep>
__device__ __forceinline__ void cp_wait() {
    asm volatile("cp.async.wait_group %0;" :: "n"(NKeep));
}

__global__ void __launch_bounds__(NTHR, 2)
stp_kernel(const float* __restrict__ inp,    // [T,B,1]
           const float* __restrict__ W_in,   // [N,1]
           const float* __restrict__ J,      // [N,N]
           const float* __restrict__ W_out,  // [1,N]
           float* __restrict__ out)
{
    extern __shared__ float sm[];
    float* part = sm + SM_PART;   // [128][RP]

    const int tid  = threadIdx.x;
    const int cta  = blockIdx.x;
    const int il   = tid & 7;           // local neuron 0..7  (lane bits 0..2)
    const int s    = tid >> 3;          // j-slice 0..31 == batch b
    const int b    = s;
    const int lane = tid & 31;
    const int warp = tid >> 5;          // 0..7, owns s in {4w..4w+3}
    const int sl   = s & 3;             // s within warp
    const int i    = cta * NLOC + il;   // global neuron
    const int c0   = cta & 15;          // chunk rotation

    float* warpTile = sm + warp * WT_F;
    const uint32_t wt_base = (uint32_t)__cvta_generic_to_shared(warpTile);

    // staging map: 4 cp.async16 per thread cover warp's 16 rows x 128B per chunk
    int goff[4], soff[4];
    #pragma unroll
    for (int o = 0; o < 4; ++o) {
        int n   = o * 32 + lane;
        int row = n >> 3;                              // 0..15
        int seg = n & 7;                               // 16B segment
        int jin = (row >> 2) * 32 + 4 * warp + (row & 3);  // j within chunk
        goff[o] = jin * B_ + seg * 4;                  // floats
        soff[o] = (row * RP + seg * 4) * 4;            // bytes within slot
    }

    // ---- this thread's 64 J coefficients in chunk-iteration order ----
    float Jreg[64];
    {
        const float* Jrow = J + (size_t)i * N_;
        #pragma unroll
        for (int cc = 0; cc < NCHUNK; ++cc) {
            const int c = (c0 + cc) & 15;
            #pragma unroll
            for (int q = 0; q < 4; ++q)
                Jreg[cc * 4 + q] = __ldg(&Jrow[c * CJ + q * 32 + s]);
        }
    }

    // ---- init state ----
    float h = 0.0f, u = U_C, x = 1.0f, hI = 0.0f;
    const float wi = __ldg(&W_in[i]);
    const float wo = __ldg(&W_out[i]);

    // ---- publish A0, pR0 ----
    float Rcur = rate_fn(h);
    {
        __stcg(&g_A[0][(size_t)i * B_ + b], u * x * Rcur);
        float sR = Rcur;
        #pragma unroll
        for (int o = 1; o <= 4; o <<= 1) sR += __shfl_xor_sync(0xffffffffu, sR, o);
        if (il == 0) __stcg(&g_pR[0][b * NCTA + cta], sR);
    }
    __syncthreads();
    if (tid == 0) {
        __threadfence();
        atomicAdd(&g_bar, 1u);
        while (*(volatile unsigned int*)&g_bar < (unsigned)NCTA) { }
        __threadfence();
    }
    __syncthreads();

    for (int t = 0; t < T_; ++t) {
        const int buf  = t & 1;
        const int nbuf = buf ^ 1;
        const float* gA = g_A[buf];

        auto stage = [&](int cc) {
            const int chunk = (c0 + cc) & 15;
            const float* src = gA + chunk * (CJ * B_);
            const uint32_t sb = wt_base + (uint32_t)((cc & 3) * SLOT_BYTES);
            #pragma unroll
            for (int o = 0; o < 4; ++o)
                cp_async16(sb + (uint32_t)soff[o], src + goff[o]);
            cp_commit();
        };

        stage(0); stage(1); stage(2);
        const float inval = __ldg(&inp[t * B_ + b]);

        unsigned long long acc2[16];
        #pragma unroll
        for (int m = 0; m < 16; ++m) acc2[m] = 0ull;

        #pragma unroll
        for (int cc = 0; cc < NCHUNK; ++cc) {
            if (cc + 3 < NCHUNK) stage(cc + 3);
            if      (cc < NCHUNK - 3) cp_wait<3>();
            else if (cc == NCHUNK - 3) cp_wait<2>();
            else if (cc == NCHUNK - 2) cp_wait<1>();
            else                       cp_wait<0>();
            __syncwarp();

            const float* Ab = warpTile + (cc & 3) * SLOT_F;
            #pragma unroll
            for (int q = 0; q < 4; ++q) {
                unsigned long long jp = pack2(Jreg[cc * 4 + q]);
                const ulonglong2* a8 = (const ulonglong2*)(Ab + (q * 4 + sl) * RP);
                #pragma unroll
                for (int e = 0; e < 8; ++e) {
                    ulonglong2 v = a8[e];
                    fma2(acc2[2 * e],     v.x, jp);
                    fma2(acc2[2 * e + 1], v.y, jp);
                }
            }
        }

        // --- combine s with s^2 (lane xor 16), dump 16 s-classes to part ---
        #pragma unroll
        for (int m = 0; m < 16; ++m) {
            unsigned long long o = __shfl_xor_sync(0xffffffffu, acc2[m], 16);
            acc2[m] = add2(acc2[m], o);
        }
        if ((s & 2) == 0) {
            const int k = (s >> 2) * 2 + (s & 1);      // 0..15
            ulonglong2* dst = (ulonglong2*)(part + (k * 8 + il) * RP);
            #pragma unroll
            for (int m = 0; m < 8; ++m)
                dst[m] = make_ulonglong2(acc2[2 * m], acc2[2 * m + 1]);
        }
        __syncthreads();

        // --- cross-CTA pR/pO gather (coalesced float4, overlaps part gather) ---
        const float4* pR4 = (const float4*)&g_pR[buf][b * NCTA + il * 32];
        float4 rv[8];
        #pragma unroll
        for (int k = 0; k < 8; ++k) rv[k] = __ldcg(&pR4[k]);
        float4 ov0 = make_float4(0.f, 0.f, 0.f, 0.f);
        float sumO = 0.0f;
        if (cta == 0) {
            const float4* pO4 = (const float4*)&g_pO[buf][b * NCTA + il * 32];
            #pragma unroll
            for (int k = 0; k < 8; ++k) {
                float4 v = __ldcg(&pO4[k]);
                sumO += v.x + v.y + v.z + v.w;
            }
            (void)ov0;
        }

        // --- gather syn: thread (il, b) sums 16 k-classes ---
        float syn = 0.0f;
        #pragma unroll
        for (int k = 0; k < 16; ++k)
            syn += part[(k * 8 + il) * RP + b];

        float sumR = 0.0f;
        #pragma unroll
        for (int k = 0; k < 8; ++k)
            sumR += rv[k].x + rv[k].y + rv[k].z + rv[k].w;
        #pragma unroll
        for (int o = 1; o <= 4; o <<= 1)
            sumR += __shfl_xor_sync(0xffffffffu, sumR, o);
        if (cta == 0) {
            #pragma unroll
            for (int o = 1; o <= 4; o <<= 1)
                sumO += __shfl_xor_sync(0xffffffffu, sumO, o);
            if (t > 0 && il == 0)
                out[OFF_OUT + (size_t)(t - 1) * B_ + b] = sumO;
        }

        // --- state update ---
        float Ie  = inval * wi;
        float RI  = rate_fn(hI);
        float dh  = (-h + syn + I_B_ + Ie) * (1.0f / TAU_) - J_EI_ * RI * (1.0f / TAU_);
        float du  = (U_C - u) * (1.0f / TAU_F) + U_C * (1.0f - u) * Rcur;
        float dx  = (1.0f - x) * (1.0f / TAU_D) - u * x * Rcur;
        float dhI = (-hI + J_IE_ * sumR) * (1.0f / TAU_);
        h  += dh  * DT_;
        u  += du  * DT_;
        x  += dx  * DT_;
        hI += dhI * DT_;

        // --- publish next-step activation + partials ---
        Rcur = rate_fn(h);
        {
            __stcg(&g_A[nbuf][(size_t)i * B_ + b], u * x * Rcur);
            float sR = Rcur;
            float sO = Rcur * wo;
            #pragma unroll
            for (int o = 1; o <= 4; o <<= 1) {
                sR += __shfl_xor_sync(0xffffffffu, sR, o);
                sO += __shfl_xor_sync(0xffffffffu, sO, o);
            }
            if (il == 0) {
                __stcg(&g_pR[nbuf][b * NCTA + cta], sR);
                __stcg(&g_pO[nbuf][b * NCTA + cta], sO);
            }
        }

        // --- barrier: arrive early, overlap output writes with propagation ---
        __syncthreads();
        if (tid == 0) {
            __threadfence();
            atomicAdd(&g_bar, 1u);
        }
        const size_t row = (size_t)(t * B_ + b) * N_ + i;
        __stcs(&out[OFF_H + row], h);
        __stcs(&out[OFF_U + row], u);
        __stcs(&out[OFF_X + row], x);
        if (cta == 0 && il == 0)
            out[OFF_HI + (size_t)t * B_ + b] = hI;
        if (tid == 0) {
            while (*(volatile unsigned int*)&g_bar < (unsigned)NCTA * (unsigned)(t + 2)) { }
            __threadfence();
        }
        __syncthreads();
    }

    // --- final outputs[T-1] (CTA 0); pO published into buffer 0 at t=511 ---
    if (cta == 0) {
        const float4* pO4 = (const float4*)&g_pO[0][b * NCTA + il * 32];
        float so = 0.0f;
        #pragma unroll
        for (int k = 0; k < 8; ++k) {
            float4 v = __ldcg(&pO4[k]);
            so += v.x + v.y + v.z + v.w;
        }
        #pragma unroll
        for (int o = 1; o <= 4; o <<= 1)
            so += __shfl_xor_sync(0xffffffffu, so, o);
        if (il == 0)
            out[OFF_OUT + (size_t)(T_ - 1) * B_ + b] = so;
    }

    // --- reset barrier counter for CUDA-graph replays ---
    __syncthreads();
    if (tid == 0) {
        __threadfence();
        unsigned v = atomicAdd(&g_exit, 1u);
        if (v == NCTA - 1) {
            g_bar  = 0;
            g_exit = 0;
            __threadfence();
        }
    }
}

extern "C" void kernel_launch(void* const* d_in, const int* in_sizes, int n_in,
                              void* d_out, int out_size) {
    const float* inp   = (const float*)d_in[0];
    const float* W_in  = (const float*)d_in[1];
    const float* J     = (const float*)d_in[2];
    const float* W_out = (const float*)d_in[3];
    float* out = (float*)d_out;

    static bool attr_done = false;
    if (!attr_done) {
        cudaFuncSetAttribute(stp_kernel,
                             cudaFuncAttributeMaxDynamicSharedMemorySize,
                             SMEM_BYTES);
        attr_done = true;
    }
    stp_kernel<<<NCTA, NTHR, SMEM_BYTES>>>(inp, W_in, J, W_out, out);
}